// round 15
// baseline (speedup 1.0000x reference)
#include <cuda_runtime.h>
#include <stdint.h>

// Fixed problem shape: features [8192, 512], labels [8192] in [0,64)
#define NB 8192
#define ND 512
#define NNEG 8
#define NLAB 64
#define HALFC 33554432u        // (8192*8192)/2
#define THRESH_RAW 0xFC000000u // raw-bits threshold == (2^23 * (1-1/64)) << 9
#define NCAP 512               // survivor cap/row (mean 128 incl same-label; 34 sigma)
#define NSLOT (NCAP / 32)
#define CLS 320                // class-list cap (mean 128; 17 sigma)

// Scratch (no cudaMalloc allowed)
__device__ unsigned char      g_lab[NB];
__device__ int                g_ccnt[NLAB];
__device__ short              g_cls[NLAB][CLS];
__device__ unsigned long long g_accum;   // fixed-point loss sum (det., order-free)
__device__ unsigned int       g_done;    // select-block completion counter

// ---------------- rotate ----------------
__host__ __device__ __forceinline__ uint32_t rotl32(uint32_t v, int r)
{
#ifdef __CUDA_ARCH__
    return __funnelshift_l(v, v, r);
#else
    return (v << r) | (v >> (32 - r));
#endif
}

// ---------------- Threefry-2x32 (20 rounds), original JAX convention ----------
__host__ __device__ __forceinline__ void threefry2x32(
    uint32_t k0, uint32_t k1, uint32_t x0, uint32_t x1,
    uint32_t* o0, uint32_t* o1)
{
    uint32_t ks2 = k0 ^ k1 ^ 0x1BD11BDAu;
    x0 += k0; x1 += k1;
#define TF_RND(r) { x0 += x1; x1 = rotl32(x1, r); x1 ^= x0; }
    TF_RND(13) TF_RND(15) TF_RND(26) TF_RND(6)  x0 += k1;  x1 += ks2 + 1u;
    TF_RND(17) TF_RND(29) TF_RND(16) TF_RND(24) x0 += ks2; x1 += k0  + 2u;
    TF_RND(13) TF_RND(15) TF_RND(26) TF_RND(6)  x0 += k0;  x1 += k1  + 3u;
    TF_RND(17) TF_RND(29) TF_RND(16) TF_RND(24) x0 += k1;  x1 += ks2 + 4u;
    TF_RND(13) TF_RND(15) TF_RND(26) TF_RND(6)  x0 += ks2; x1 += k0  + 5u;
#undef TF_RND
    *o0 = x0; *o1 = x1;
}

// Pre-keyed variant: caller supplies the INITIAL STATE (x0 = n + k0,
// x1 = n + HALFC + k1 with k1h precomputed); key schedule uses TRUE k0/k1/ks2.
// Bit-identical to threefry2x32(k0,k1,n,n+HALFC).
__device__ __forceinline__ void threefry_state(
    uint32_t k0, uint32_t k1, uint32_t ks2, uint32_t x0, uint32_t x1,
    uint32_t* o0, uint32_t* o1)
{
#define TF_RND(r) { x0 += x1; x1 = rotl32(x1, r); x1 ^= x0; }
    TF_RND(13) TF_RND(15) TF_RND(26) TF_RND(6)  x0 += k1;  x1 += ks2 + 1u;
    TF_RND(17) TF_RND(29) TF_RND(16) TF_RND(24) x0 += ks2; x1 += k0  + 2u;
    TF_RND(13) TF_RND(15) TF_RND(26) TF_RND(6)  x0 += k0;  x1 += k1  + 3u;
    TF_RND(17) TF_RND(29) TF_RND(16) TF_RND(24) x0 += k1;  x1 += ks2 + 4u;
    TF_RND(13) TF_RND(15) TF_RND(26) TF_RND(6)  x0 += ks2; x1 += k0  + 5u;
#undef TF_RND
    *o0 = x0; *o1 = x1;
}

// ordering of gumbel == ordering of (bits>>9); tie -> lower j wins.
__device__ __forceinline__ unsigned long long pack_key(uint32_t bits, int j)
{
    return ((unsigned long long)(bits >> 9) << 13) |
           (unsigned long long)(NB - 1 - j);
}

__device__ __forceinline__ unsigned long long warp_max_u64(unsigned long long v)
{
    #pragma unroll
    for (int o = 16; o; o >>= 1) {
        unsigned long long u = __shfl_xor_sync(0xffffffffu, v, o);
        if (u > v) v = u;
    }
    return v;
}

// ---------------- Kernel 0: prep — one block per label ----------------
__global__ __launch_bounds__(256) void k_prep(const long long* __restrict__ labels)
{
    const int myLab = blockIdx.x;          // 0..63
    __shared__ int scnt;
    if (threadIdx.x == 0) {
        scnt = 0;
        if (myLab == 0) { g_accum = 0ull; g_done = 0u; }
    }
    __syncthreads();

    for (int i = threadIdx.x; i < NB; i += 256) {
        int lab = (int)labels[i] & (NLAB - 1);
        if (myLab == 0) g_lab[i] = (unsigned char)lab;
        if (lab == myLab) {
            int p = atomicAdd(&scnt, 1);
            if (p < CLS) g_cls[myLab][p] = (short)i;
        }
    }
    __syncthreads();
    if (threadIdx.x == 0) g_ccnt[myLab] = min(scnt, CLS);
}

// ---------------- Kernel 1: row-PAIR selection + fused loss + fused mean -----
// Block b: rows i_lo=b, i_hi=b+NB/2 (counter pair shares one threefry block:
// o0 -> row lo, o1 -> row hi). Hot loop = threefry + threshold + BRANCHLESS
// predicated push (R14 ballot reverted: it cost ~10 unconditional instrs/q).
__global__ __launch_bounds__(256, 7) void k_select_loss(
    const float* __restrict__ feat, float* __restrict__ out,
    uint32_t kp0, uint32_t kp1, uint32_t kp1h,
    uint32_t kn0, uint32_t kn1, uint32_t kn1h)
{
    const int i_lo = blockIdx.x;           // 0..4095
    const int i_hi = i_lo + (NB >> 1);
    const int tid = threadIdx.x, lane = tid & 31, wid = tid >> 5;
    const uint32_t ksn = kn0 ^ kn1 ^ 0x1BD11BDAu;
    const uint32_t ksp = kp0 ^ kp1 ^ 0x1BD11BDAu;

    __shared__ unsigned long long nsurv[2][NCAP];         // 8 KB
    __shared__ int ncnt[2];
    __shared__ unsigned long long spos[2][8];
    __shared__ int    sidx[2][1 + NNEG];                  // partner indices
    __shared__ float4 srow4[2][ND / 4];                   // anchor rows (4 KB)
    __shared__ float  sdots[2][1 + NNEG];
    __shared__ float  ssqp[2][1 + NNEG];
    __shared__ float  sanc[2];

    if (tid < 2) ncnt[tid] = 0;
    __syncthreads();

    const uint32_t nbase = (uint32_t)i_lo * (uint32_t)NB;

    // ---- hot loop: 8192 threefry blocks, threshold + predicated push ----
    for (int jb = tid * 4; jb < NB; jb += 1024) {
        #pragma unroll
        for (int q = 0; q < 4; q++) {
            int j = jb + q;
            uint32_t n = nbase + (uint32_t)j;
            uint32_t o0, o1;
            threefry_state(kn0, kn1, ksn, n + kn0, n + kn1h, &o0, &o1);
            // branchless: predicated atomic, guarded store (no BSSY envelope)
            uint32_t p0 = (o0 >= THRESH_RAW)
                        ? (uint32_t)atomicAdd(&ncnt[0], 1) : 0xFFFFFFFFu;
            if (p0 < NCAP) nsurv[0][p0] = pack_key(o0, j);
            uint32_t p1 = (o1 >= THRESH_RAW)
                        ? (uint32_t)atomicAdd(&ncnt[1], 1) : 0xFFFFFFFFu;
            if (p1 < NCAP) nsurv[1][p1] = pack_key(o1, j);
        }
    }

    const unsigned int lab_lo = g_lab[i_lo];
    const unsigned int lab_hi = g_lab[i_hi];

    // ---- sparse positive loops from global class lists (kp key) ----
    unsigned long long bp_lo = 0ull, bp_hi = 0ull;
    {
        int c0 = g_ccnt[lab_lo];
        for (int t = tid; t < c0; t += 256) {
            int j = g_cls[lab_lo][t];
            if (j != i_lo) {
                uint32_t n = nbase + (uint32_t)j, o0, o1;
                threefry_state(kp0, kp1, ksp, n + kp0, n + kp1h, &o0, &o1);
                unsigned long long p = pack_key(o0, j);
                if (p > bp_lo) bp_lo = p;
            }
        }
        int c1 = g_ccnt[lab_hi];
        for (int t = tid; t < c1; t += 256) {
            int j = g_cls[lab_hi][t];
            if (j != i_hi) {
                uint32_t n = nbase + (uint32_t)j, o0, o1;
                threefry_state(kp0, kp1, ksp, n + kp0, n + kp1h, &o0, &o1);
                unsigned long long p = pack_key(o1, j);
                if (p > bp_hi) bp_hi = p;
            }
        }
    }
    bp_lo = warp_max_u64(bp_lo);
    bp_hi = warp_max_u64(bp_hi);
    if (lane == 0) { spos[0][wid] = bp_lo; spos[1][wid] = bp_hi; }
    __syncthreads();

    // ---- tail: warps 0-1 filter + extract top-8 + pos; warps 2-7 preload rows
    if (wid < 2) {
        const int row = wid;
        const unsigned int lab_row = row ? lab_hi : lab_lo;
        int cnt = min(ncnt[row], NCAP);

        unsigned long long v[NSLOT];
        #pragma unroll
        for (int s = 0; s < NSLOT; s++) {
            int idx = lane + 32 * s;
            unsigned long long key = 0ull;
            if (idx < cnt) {
                key = nsurv[row][idx];
                int j = NB - 1 - (int)(key & 0x1FFFull);
                if ((unsigned int)g_lab[j] == lab_row) key = 0ull;  // drop same-label
            }
            v[s] = key;
        }
        #pragma unroll
        for (int r = 0; r < NNEG; r++) {
            unsigned long long loc = 0ull;
            #pragma unroll
            for (int s = 0; s < NSLOT; s++) if (v[s] > loc) loc = v[s];
            unsigned long long g = warp_max_u64(loc);
            #pragma unroll
            for (int s = 0; s < NSLOT; s++) if (v[s] == g) v[s] = 0ull;  // unique pop
            if (lane == 0) sidx[row][1 + r] = NB - 1 - (int)(g & 0x1FFFull);
        }
        unsigned long long bp = (lane < 8) ? spos[row][lane] : 0ull;
        bp = warp_max_u64(bp);
        if (lane == 0)
            sidx[row][0] = (bp == 0ull) ? 0 : (NB - 1 - (int)(bp & 0x1FFFull));
    } else {
        // load anchor rows i_lo, i_hi into smem: 256 float4 by 192 threads
        int idx = tid - 64;
        for (int c = idx; c < 2 * (ND / 4); c += 192) {
            int row = c >> 7;                 // 128 float4 per row
            int col = c & 127;
            const int i_row = row ? i_hi : i_lo;
            srow4[row][col] =
                ((const float4*)(feat + (size_t)i_row * ND))[col];
        }
    }
    __syncthreads();

    // ---- tasks: 0..17 = dots (+ partner ssq); 18,19 = anchor ssq ----
    for (int t = wid; t < 20; t += 8) {
        if (t < 18) {
            int row  = t / (1 + NNEG);
            int slot = t % (1 + NNEG);
            int j = sidx[row][slot];
            const float4* fr = (const float4*)(feat + (size_t)j * ND);
            const float4* ar = srow4[row];
            float acc = 0.0f, sq = 0.0f;
            #pragma unroll
            for (int k = 0; k < 4; k++) {
                float4 a = ar[lane + 32 * k];
                float4 b = fr[lane + 32 * k];
                acc += a.x * b.x + a.y * b.y + a.z * b.z + a.w * b.w;
                sq  += b.x * b.x + b.y * b.y + b.z * b.z + b.w * b.w;
            }
            #pragma unroll
            for (int o = 16; o; o >>= 1) {
                acc += __shfl_xor_sync(0xffffffffu, acc, o);
                sq  += __shfl_xor_sync(0xffffffffu, sq,  o);
            }
            if (lane == 0) { sdots[row][slot] = acc; ssqp[row][slot] = sq; }
        } else {
            int row = t - 18;
            const float4* ar = srow4[row];
            float sq = 0.0f;
            #pragma unroll
            for (int k = 0; k < 4; k++) {
                float4 a = ar[lane + 32 * k];
                sq += a.x * a.x + a.y * a.y + a.z * a.z + a.w * a.w;
            }
            #pragma unroll
            for (int o = 16; o; o >>= 1) sq += __shfl_xor_sync(0xffffffffu, sq, o);
            if (lane == 0) sanc[row] = sq;
        }
    }
    __syncthreads();

    // ---- loss epilogue: thread 0 -> row lo, thread 1 -> row hi ----
    if (tid < 2) {
        const int row = tid;
        float inv_i = 1.0f / fmaxf(sqrtf(sanc[row]), 1e-12f);
        float sims[1 + NNEG];
        #pragma unroll
        for (int q = 0; q < 1 + NNEG; q++) {
            float inv_j = 1.0f / fmaxf(sqrtf(ssqp[row][q]), 1e-12f);
            sims[q] = sdots[row][q] * inv_i * inv_j;
        }
        float pos = sims[0] * 2.0f;          // / TEMPERATURE (0.5)
        float s[NNEG];
        #pragma unroll
        for (int q = 0; q < NNEG; q++) s[q] = sims[1 + q];
        float hard[3];
        #pragma unroll
        for (int r = 0; r < 3; r++) {        // stable top-3 (lower index wins)
            int bi = 0; float bv = s[0];
            #pragma unroll
            for (int q = 1; q < NNEG; q++) if (s[q] > bv) { bv = s[q]; bi = q; }
            hard[r] = bv * 2.0f;
            s[bi] = -3.0e38f;
        }
        float mx = fmaxf(fmaxf(pos, hard[0]), fmaxf(hard[1], hard[2]));
        float sum = expf(pos - mx) + expf(hard[0] - mx) +
                    expf(hard[1] - mx) + expf(hard[2] - mx);
        float loss = mx + logf(sum) - pos;   // >= 0 always
        unsigned long long q64 = (unsigned long long)((double)loss * 4294967296.0);
        atomicAdd(&g_accum, q64);
    }
    __syncthreads();                         // both adds of this block done

    // ---- last block emits the mean (integer sum -> deterministic) ----
    if (tid == 0) {
        __threadfence();
        unsigned int prev = atomicAdd(&g_done, 1u);
        if (prev == (unsigned int)(NB / 2 - 1)) {
            unsigned long long acc = atomicAdd(&g_accum, 0ull);
            out[0] = (float)((double)acc * (1.0 / 4294967296.0) / (double)NB);
        }
    }
}

// ---------------- Launch ----------------
extern "C" void kernel_launch(void* const* d_in, const int* in_sizes, int n_in,
                              void* d_out, int out_size)
{
    const float*     feat   = (const float*)d_in[0];
    const long long* labels = (const long long*)d_in[1];

    // seed 42 -> raw key (0, 42); original split: counts iota(4) -> pairs
    // (0,2),(1,3); kp=(a0,a1), kn=(b0,b1)
    uint32_t a0, b0, a1, b1;
    threefry2x32(0u, 42u, 0u, 2u, &a0, &b0);
    threefry2x32(0u, 42u, 1u, 3u, &a1, &b1);
    uint32_t kp0 = a0, kp1 = a1, kn0 = b0, kn1 = b1;
    // prefold HALFC into the INITIAL-STATE constant only (key schedule intact)
    uint32_t kp1h = kp1 + HALFC, kn1h = kn1 + HALFC;

    k_prep       <<<NLAB, 256>>>(labels);
    k_select_loss<<<NB / 2, 256>>>(feat, (float*)d_out,
                                   kp0, kp1, kp1h, kn0, kn1, kn1h);
}

// round 17
// speedup vs baseline: 1.6518x; 1.6518x over previous
#include <cuda_runtime.h>
#include <stdint.h>

// Fixed problem shape: features [8192, 512], labels [8192] in [0,64)
#define NB 8192
#define ND 512
#define NNEG 8
#define NLAB 64
#define HALFC 33554432u        // (8192*8192)/2
#define THRESH_RAW 0xFC000000u // raw-bits threshold == (2^23 * (1-1/64)) << 9
#define NCAP 512               // survivor cap/row (mean ~128; 34 sigma)
#define NSLOT (NCAP / 32)
#define CLS 320                // class-list cap (mean 128; 17 sigma)

// Scratch (no cudaMalloc allowed)
__device__ unsigned char      g_lab[NB];
__device__ int                g_ccnt[NLAB];
__device__ short              g_cls[NLAB][CLS];
__device__ unsigned long long g_accum;   // fixed-point loss sum (det., order-free)

// ---------------- rotate ----------------
__host__ __device__ __forceinline__ uint32_t rotl32(uint32_t v, int r)
{
#ifdef __CUDA_ARCH__
    return __funnelshift_l(v, v, r);
#else
    return (v << r) | (v >> (32 - r));
#endif
}

// ---------------- Threefry-2x32 (20 rounds), original JAX convention ----------
__host__ __device__ __forceinline__ void threefry2x32(
    uint32_t k0, uint32_t k1, uint32_t x0, uint32_t x1,
    uint32_t* o0, uint32_t* o1)
{
    uint32_t ks2 = k0 ^ k1 ^ 0x1BD11BDAu;
    x0 += k0; x1 += k1;
#define TF_RND(r) { x0 += x1; x1 = rotl32(x1, r); x1 ^= x0; }
    TF_RND(13) TF_RND(15) TF_RND(26) TF_RND(6)  x0 += k1;  x1 += ks2 + 1u;
    TF_RND(17) TF_RND(29) TF_RND(16) TF_RND(24) x0 += ks2; x1 += k0  + 2u;
    TF_RND(13) TF_RND(15) TF_RND(26) TF_RND(6)  x0 += k0;  x1 += k1  + 3u;
    TF_RND(17) TF_RND(29) TF_RND(16) TF_RND(24) x0 += k1;  x1 += ks2 + 4u;
    TF_RND(13) TF_RND(15) TF_RND(26) TF_RND(6)  x0 += ks2; x1 += k0  + 5u;
#undef TF_RND
    *o0 = x0; *o1 = x1;
}

// Pre-keyed variant: caller supplies the INITIAL STATE (x0 = n + k0,
// x1 = n + HALFC + k1 with k1h precomputed); key schedule uses TRUE k0/k1/ks2.
// Bit-identical to threefry2x32(k0,k1,n,n+HALFC).
__device__ __forceinline__ void threefry_state(
    uint32_t k0, uint32_t k1, uint32_t ks2, uint32_t x0, uint32_t x1,
    uint32_t* o0, uint32_t* o1)
{
#define TF_RND(r) { x0 += x1; x1 = rotl32(x1, r); x1 ^= x0; }
    TF_RND(13) TF_RND(15) TF_RND(26) TF_RND(6)  x0 += k1;  x1 += ks2 + 1u;
    TF_RND(17) TF_RND(29) TF_RND(16) TF_RND(24) x0 += ks2; x1 += k0  + 2u;
    TF_RND(13) TF_RND(15) TF_RND(26) TF_RND(6)  x0 += k0;  x1 += k1  + 3u;
    TF_RND(17) TF_RND(29) TF_RND(16) TF_RND(24) x0 += k1;  x1 += ks2 + 4u;
    TF_RND(13) TF_RND(15) TF_RND(26) TF_RND(6)  x0 += ks2; x1 += k0  + 5u;
#undef TF_RND
    *o0 = x0; *o1 = x1;
}

// ordering of gumbel == ordering of (bits>>9); tie -> lower j wins.
__device__ __forceinline__ unsigned long long pack_key(uint32_t bits, int j)
{
    return ((unsigned long long)(bits >> 9) << 13) |
           (unsigned long long)(NB - 1 - j);
}

__device__ __forceinline__ unsigned long long warp_max_u64(unsigned long long v)
{
    #pragma unroll
    for (int o = 16; o; o >>= 1) {
        unsigned long long u = __shfl_xor_sync(0xffffffffu, v, o);
        if (u > v) v = u;
    }
    return v;
}

// ---------------- Kernel 0: prep — one block per label ----------------
__global__ __launch_bounds__(256) void k_prep(const long long* __restrict__ labels)
{
    const int myLab = blockIdx.x;          // 0..63
    __shared__ int scnt;
    if (threadIdx.x == 0) {
        scnt = 0;
        if (myLab == 0) g_accum = 0ull;    // reset for graph replay
    }
    __syncthreads();

    for (int i = threadIdx.x; i < NB; i += 256) {
        int lab = (int)labels[i] & (NLAB - 1);
        if (myLab == 0) g_lab[i] = (unsigned char)lab;
        if (lab == myLab) {
            int p = atomicAdd(&scnt, 1);
            if (p < CLS) g_cls[myLab][p] = (short)i;
        }
    }
    __syncthreads();
    if (threadIdx.x == 0) g_ccnt[myLab] = min(scnt, CLS);
}

// ---------------- Kernel 1: row-PAIR selection + fused loss ----------------
// Block b: rows i_lo=b, i_hi=b+NB/2 (counter pair shares one threefry block:
// o0 -> row lo, o1 -> row hi). Hot loop = threefry + threshold + branchless
// predicated push. Natural register allocation (R15 lesson: forcing regs
// below ~40 spills in the hot loop -> 250us). Mean emitted by a separate
// kernel: the R12-R16 fused-mean pattern raced (threadfence only orders the
// CALLING thread; tid1's g_accum atomic could still be in flight when the
// last block read the sum -> run-to-run rel_err jitter up to ~1.2e-3).
__global__ __launch_bounds__(256) void k_select_loss(
    const float* __restrict__ feat,
    uint32_t kp0, uint32_t kp1, uint32_t kp1h,
    uint32_t kn0, uint32_t kn1, uint32_t kn1h)
{
    const int i_lo = blockIdx.x;           // 0..4095
    const int i_hi = i_lo + (NB >> 1);
    const int tid = threadIdx.x, lane = tid & 31, wid = tid >> 5;
    const uint32_t ksn = kn0 ^ kn1 ^ 0x1BD11BDAu;
    const uint32_t ksp = kp0 ^ kp1 ^ 0x1BD11BDAu;

    __shared__ unsigned long long nsurv[2][NCAP];         // 8 KB
    __shared__ int ncnt[2];
    __shared__ unsigned long long spos[2][8];
    __shared__ int    sidx[2][1 + NNEG];                  // partner indices
    __shared__ float4 srow4[2][ND / 4];                   // anchor rows (4 KB)
    __shared__ float  sdots[2][1 + NNEG];
    __shared__ float  ssqp[2][1 + NNEG];
    __shared__ float  sanc[2];

    if (tid < 2) ncnt[tid] = 0;
    __syncthreads();

    const uint32_t nbase = (uint32_t)i_lo * (uint32_t)NB;

    // ---- hot loop: 8192 threefry blocks, threshold + predicated push ----
    for (int jb = tid * 4; jb < NB; jb += 1024) {
        #pragma unroll
        for (int q = 0; q < 4; q++) {
            int j = jb + q;
            uint32_t n = nbase + (uint32_t)j;
            uint32_t o0, o1;
            threefry_state(kn0, kn1, ksn, n + kn0, n + kn1h, &o0, &o1);
            uint32_t p0 = (o0 >= THRESH_RAW)
                        ? (uint32_t)atomicAdd(&ncnt[0], 1) : 0xFFFFFFFFu;
            if (p0 < NCAP) nsurv[0][p0] = pack_key(o0, j);
            uint32_t p1 = (o1 >= THRESH_RAW)
                        ? (uint32_t)atomicAdd(&ncnt[1], 1) : 0xFFFFFFFFu;
            if (p1 < NCAP) nsurv[1][p1] = pack_key(o1, j);
        }
    }

    const unsigned int lab_lo = g_lab[i_lo];
    const unsigned int lab_hi = g_lab[i_hi];

    // ---- sparse positive loops from global class lists (kp key) ----
    unsigned long long bp_lo = 0ull, bp_hi = 0ull;
    {
        int c0 = g_ccnt[lab_lo];
        for (int t = tid; t < c0; t += 256) {
            int j = g_cls[lab_lo][t];
            if (j != i_lo) {
                uint32_t n = nbase + (uint32_t)j, o0, o1;
                threefry_state(kp0, kp1, ksp, n + kp0, n + kp1h, &o0, &o1);
                unsigned long long p = pack_key(o0, j);
                if (p > bp_lo) bp_lo = p;
            }
        }
        int c1 = g_ccnt[lab_hi];
        for (int t = tid; t < c1; t += 256) {
            int j = g_cls[lab_hi][t];
            if (j != i_hi) {
                uint32_t n = nbase + (uint32_t)j, o0, o1;
                threefry_state(kp0, kp1, ksp, n + kp0, n + kp1h, &o0, &o1);
                unsigned long long p = pack_key(o1, j);
                if (p > bp_hi) bp_hi = p;
            }
        }
    }
    bp_lo = warp_max_u64(bp_lo);
    bp_hi = warp_max_u64(bp_hi);
    if (lane == 0) { spos[0][wid] = bp_lo; spos[1][wid] = bp_hi; }
    __syncthreads();

    // ---- tail: warps 0-1 filter + extract top-8 + pos; warps 2-7 preload rows
    if (wid < 2) {
        const int row = wid;
        const unsigned int lab_row = row ? lab_hi : lab_lo;
        int cnt = min(ncnt[row], NCAP);

        unsigned long long v[NSLOT];
        #pragma unroll
        for (int s = 0; s < NSLOT; s++) {
            int idx = lane + 32 * s;
            unsigned long long key = 0ull;
            if (idx < cnt) {
                key = nsurv[row][idx];
                int j = NB - 1 - (int)(key & 0x1FFFull);
                if ((unsigned int)g_lab[j] == lab_row) key = 0ull;  // drop same-label
            }
            v[s] = key;
        }
        #pragma unroll
        for (int r = 0; r < NNEG; r++) {
            unsigned long long loc = 0ull;
            #pragma unroll
            for (int s = 0; s < NSLOT; s++) if (v[s] > loc) loc = v[s];
            unsigned long long g = warp_max_u64(loc);
            #pragma unroll
            for (int s = 0; s < NSLOT; s++) if (v[s] == g) v[s] = 0ull;  // unique pop
            if (lane == 0) sidx[row][1 + r] = NB - 1 - (int)(g & 0x1FFFull);
        }
        unsigned long long bp = (lane < 8) ? spos[row][lane] : 0ull;
        bp = warp_max_u64(bp);
        if (lane == 0)
            sidx[row][0] = (bp == 0ull) ? 0 : (NB - 1 - (int)(bp & 0x1FFFull));
    } else {
        // load anchor rows i_lo, i_hi into smem: 256 float4 by 192 threads
        int idx = tid - 64;
        for (int c = idx; c < 2 * (ND / 4); c += 192) {
            int row = c >> 7;                 // 128 float4 per row
            int col = c & 127;
            const int i_row = row ? i_hi : i_lo;
            srow4[row][col] =
                ((const float4*)(feat + (size_t)i_row * ND))[col];
        }
    }
    __syncthreads();

    // ---- tasks: 0..17 = dots (+ partner ssq); 18,19 = anchor ssq ----
    for (int t = wid; t < 20; t += 8) {
        if (t < 18) {
            int row  = t / (1 + NNEG);
            int slot = t % (1 + NNEG);
            int j = sidx[row][slot];
            const float4* fr = (const float4*)(feat + (size_t)j * ND);
            const float4* ar = srow4[row];
            float acc = 0.0f, sq = 0.0f;
            #pragma unroll
            for (int k = 0; k < 4; k++) {
                float4 a = ar[lane + 32 * k];
                float4 b = fr[lane + 32 * k];
                acc += a.x * b.x + a.y * b.y + a.z * b.z + a.w * b.w;
                sq  += b.x * b.x + b.y * b.y + b.z * b.z + b.w * b.w;
            }
            #pragma unroll
            for (int o = 16; o; o >>= 1) {
                acc += __shfl_xor_sync(0xffffffffu, acc, o);
                sq  += __shfl_xor_sync(0xffffffffu, sq,  o);
            }
            if (lane == 0) { sdots[row][slot] = acc; ssqp[row][slot] = sq; }
        } else {
            int row = t - 18;
            const float4* ar = srow4[row];
            float sq = 0.0f;
            #pragma unroll
            for (int k = 0; k < 4; k++) {
                float4 a = ar[lane + 32 * k];
                sq += a.x * a.x + a.y * a.y + a.z * a.z + a.w * a.w;
            }
            #pragma unroll
            for (int o = 16; o; o >>= 1) sq += __shfl_xor_sync(0xffffffffu, sq, o);
            if (lane == 0) sanc[row] = sq;
        }
    }
    __syncthreads();

    // ---- loss epilogue: thread 0 -> row lo, thread 1 -> row hi ----
    if (tid < 2) {
        const int row = tid;
        float inv_i = 1.0f / fmaxf(sqrtf(sanc[row]), 1e-12f);
        float sims[1 + NNEG];
        #pragma unroll
        for (int q = 0; q < 1 + NNEG; q++) {
            float inv_j = 1.0f / fmaxf(sqrtf(ssqp[row][q]), 1e-12f);
            sims[q] = sdots[row][q] * inv_i * inv_j;
        }
        float pos = sims[0] * 2.0f;          // / TEMPERATURE (0.5)
        float s[NNEG];
        #pragma unroll
        for (int q = 0; q < NNEG; q++) s[q] = sims[1 + q];
        float hard[3];
        #pragma unroll
        for (int r = 0; r < 3; r++) {        // stable top-3 (lower index wins)
            int bi = 0; float bv = s[0];
            #pragma unroll
            for (int q = 1; q < NNEG; q++) if (s[q] > bv) { bv = s[q]; bi = q; }
            hard[r] = bv * 2.0f;
            s[bi] = -3.0e38f;
        }
        float mx = fmaxf(fmaxf(pos, hard[0]), fmaxf(hard[1], hard[2]));
        float sum = expf(pos - mx) + expf(hard[0] - mx) +
                    expf(hard[1] - mx) + expf(hard[2] - mx);
        float loss = mx + logf(sum) - pos;   // >= 0 always
        // fixed-point accumulate: integer atomic sum is order-independent.
        // Completion guaranteed by the KERNEL BOUNDARY before k_final.
        unsigned long long q64 = (unsigned long long)((double)loss * 4294967296.0);
        atomicAdd(&g_accum, q64);
    }
}

// ---------------- Kernel 2: finalize mean (race-free across launch) ----------
__global__ void k_final(float* __restrict__ out)
{
    out[0] = (float)((double)g_accum * (1.0 / 4294967296.0) / (double)NB);
}

// ---------------- Launch ----------------
extern "C" void kernel_launch(void* const* d_in, const int* in_sizes, int n_in,
                              void* d_out, int out_size)
{
    const float*     feat   = (const float*)d_in[0];
    const long long* labels = (const long long*)d_in[1];

    // seed 42 -> raw key (0, 42); original split: counts iota(4) -> pairs
    // (0,2),(1,3); kp=(a0,a1), kn=(b0,b1)
    uint32_t a0, b0, a1, b1;
    threefry2x32(0u, 42u, 0u, 2u, &a0, &b0);
    threefry2x32(0u, 42u, 1u, 3u, &a1, &b1);
    uint32_t kp0 = a0, kp1 = a1, kn0 = b0, kn1 = b1;
    // prefold HALFC into the INITIAL-STATE constant only (key schedule intact)
    uint32_t kp1h = kp1 + HALFC, kn1h = kn1 + HALFC;

    k_prep       <<<NLAB, 256>>>(labels);
    k_select_loss<<<NB / 2, 256>>>(feat, kp0, kp1, kp1h, kn0, kn1, kn1h);
    k_final      <<<1, 1>>>((float*)d_out);
}